// round 4
// baseline (speedup 1.0000x reference)
#include <cuda_runtime.h>
#include <cstdint>

#define Bn 16
#define Vn 40000
#define Cn 128
#define Hn 56
#define Wn 56
#define En 120000
#define Mn (Bn*Vn)          // 640000
#define HWn (Hn*Wn)         // 3136
#define NTILES (Mn/32)      // 20000 (40000%32==0 -> tiles never cross batches)
#define TPB 1250            // tiles per batch

// ---------------- device scratch ----------------
__device__ float g_imgT[(size_t)Bn*HWn*Cn];     // [B,H,W,C]
__device__ float g_A [81920000];                // G, later U (tf32-rounded)
__device__ float g_Dk[81920000];                // D (tf32-rounded; residual)
__device__ float g_Bt[6*128*128];               // transposed tf32 weights [n][k]

__device__ int g_deg[Vn];
__device__ int g_cursor[Vn];
__device__ int g_rowptr[Vn+1];
__device__ int g_col[2*En];

// ---------------- helpers ----------------
__device__ __forceinline__ float rnd_tf32(float x) {
    float r;
    asm("cvt.rna.tf32.f32 %0, %1;" : "=f"(r) : "f"(x));
    return r;
}

__device__ __forceinline__ uint32_t smem_u32(const void* p) {
    uint32_t a;
    asm("{ .reg .u64 t; cvta.to.shared.u64 t, %1; cvt.u32.u64 %0, t; }" : "=r"(a) : "l"(p));
    return a;
}

__device__ __forceinline__ void mma_tf32(float* c, const uint32_t* a, const uint32_t* b) {
    asm volatile(
        "mma.sync.aligned.m16n8k8.row.col.f32.tf32.tf32.f32 "
        "{%0,%1,%2,%3}, {%4,%5,%6,%7}, {%8,%9}, {%0,%1,%2,%3};"
        : "+f"(c[0]), "+f"(c[1]), "+f"(c[2]), "+f"(c[3])
        : "r"(a[0]), "r"(a[1]), "r"(a[2]), "r"(a[3]), "r"(b[0]), "r"(b[1]));
}

// ---------------- CSR build ----------------
__global__ void zero_csr() {
    int i = blockIdx.x*blockDim.x + threadIdx.x;
    if (i < Vn) { g_deg[i] = 0; g_cursor[i] = 0; }
}

__global__ void count_edges(const int* __restrict__ edges) {
    int e = blockIdx.x*blockDim.x + threadIdx.x;
    if (e < En) {
        atomicAdd(&g_deg[edges[2*e+0]], 1);
        atomicAdd(&g_deg[edges[2*e+1]], 1);
    }
}

__global__ void scan_kernel() {
    __shared__ int partial[1024];
    int t = threadIdx.x;
    const int CH = (Vn + 1023) / 1024;
    int base = t * CH;
    int s = 0;
    for (int i = 0; i < CH; i++) {
        int idx = base + i;
        if (idx < Vn) s += g_deg[idx];
    }
    partial[t] = s;
    __syncthreads();
    for (int off = 1; off < 1024; off <<= 1) {
        int v = 0;
        if (t >= off) v = partial[t - off];
        __syncthreads();
        partial[t] += v;
        __syncthreads();
    }
    int run = (t == 0) ? 0 : partial[t-1];
    for (int i = 0; i < CH; i++) {
        int idx = base + i;
        if (idx < Vn) { g_rowptr[idx] = run; run += g_deg[idx]; }
    }
    if (t == 1023) g_rowptr[Vn] = run;
}

__global__ void fill_edges(const int* __restrict__ edges) {
    int e = blockIdx.x*blockDim.x + threadIdx.x;
    if (e < En) {
        int i = edges[2*e+0], j = edges[2*e+1];
        int p = atomicAdd(&g_cursor[i], 1);
        g_col[g_rowptr[i] + p] = j;
        int q = atomicAdd(&g_cursor[j], 1);
        g_col[g_rowptr[j] + q] = i;
    }
}

// ---------------- weight prep: Bt[n*128+k] = round_tf32(W[k*128+n]) ----------------
__global__ void prep_weights(const float* __restrict__ W, float* __restrict__ Bt) {
    int i = blockIdx.x*blockDim.x + threadIdx.x;   // 16384
    int n = i >> 7, k = i & 127;
    Bt[i] = rnd_tf32(W[k*128 + n]);
}

// ---------------- image transpose [B,C,H,W] -> [B,H,W,C] ----------------
__global__ void transpose_img(const float* __restrict__ img) {
    __shared__ float tile[32][33];
    int b   = blockIdx.z;
    int hw0 = blockIdx.x * 32;
    int c0  = blockIdx.y * 32;
    int tx = threadIdx.x, ty = threadIdx.y;
    int hw = hw0 + tx, c = c0 + ty;
    if (hw < HWn)
        tile[ty][tx] = img[((size_t)(b*Cn + c))*HWn + hw];
    __syncthreads();
    int hw2 = hw0 + ty, c2 = c0 + tx;
    if (hw2 < HWn)
        g_imgT[((size_t)(b*HWn + hw2))*Cn + c2] = tile[tx][ty];
}

// ---------------- vert_align + add padded -> g_A (tf32-rounded) ----------------
__global__ void vert_align_kernel(const float* __restrict__ vpos,
                                  const float* __restrict__ vpad) {
    int gw   = (blockIdx.x*blockDim.x + threadIdx.x) >> 5;
    int lane = threadIdx.x & 31;
    if (gw >= Mn) return;
    int b = gw / Vn;

    float px = vpos[(size_t)gw*3 + 0];
    float py = vpos[(size_t)gw*3 + 1];
    float x = (px + 1.0f) * 0.5f * (float)(Wn - 1);
    float y = (py + 1.0f) * 0.5f * (float)(Hn - 1);
    float x0f = floorf(x), y0f = floorf(y);
    float wx1 = x - x0f, wx0 = 1.0f - wx1;
    float wy1 = y - y0f, wy0 = 1.0f - wy1;
    int x0 = (int)x0f, y0 = (int)y0f;

    float4 acc = ((const float4*)(vpad + (size_t)gw*Cn))[lane];

    int   xs_[4] = { x0, x0+1, x0,   x0+1 };
    int   ys_[4] = { y0, y0,   y0+1, y0+1 };
    float ws_[4] = { wx0*wy0, wx1*wy0, wx0*wy1, wx1*wy1 };

    #pragma unroll
    for (int t = 0; t < 4; t++) {
        int xi = xs_[t], yi = ys_[t];
        bool inb = (xi >= 0) && (xi < Wn) && (yi >= 0) && (yi < Hn);
        float wgt = inb ? ws_[t] : 0.0f;
        if (wgt != 0.0f) {
            float4 f = ((const float4*)(g_imgT + ((size_t)((b*Hn + yi)*Wn + xi))*Cn))[lane];
            acc.x += wgt*f.x; acc.y += wgt*f.y; acc.z += wgt*f.z; acc.w += wgt*f.w;
        }
    }
    acc.x = rnd_tf32(acc.x); acc.y = rnd_tf32(acc.y);
    acc.z = rnd_tf32(acc.z); acc.w = rnd_tf32(acc.w);
    ((float4*)(g_A + (size_t)gw*Cn))[lane] = acc;
}

// ---------------- fused graph-conv GEMM ----------------
// D[32-tile] = [X_tile | S_tile] (32x256) @ Wcat^T (256x128) + b0 (+Dadd)
// SMEM floats: sB[128n x 256k] swz | sA[2][32 x 256] swz | sRed[4][32][40] | sbias[128]
#define SB_OFF    0
#define SA_OFF    32768
#define SRED_OFF  49152
#define SBIAS_OFF 54272
#define SMEM_FLOATS 54400      // 217600 B

__device__ __forceinline__ void issue_x(const float* __restrict__ X, int t, int buf,
                                        int tid, uint32_t sA_u) {
    const float* src0 = X + (size_t)t * (32 * 128);
    uint32_t dbase = sA_u + (uint32_t)buf * 32768u;   // bytes (8192 floats per stage)
    #pragma unroll
    for (int j = 0; j < 4; j++) {
        int i4 = tid + j*256;                // 0..1023 float4
        int row = i4 >> 5;                   // 0..31
        int kq  = (i4 & 31) << 2;            // 0..124
        uint32_t off = (uint32_t)((row << 8) + (kq ^ ((row & 7) << 2))) * 4u;
        asm volatile("cp.async.cg.shared.global [%0], [%1], 16;"
            :: "r"(dbase + off), "l"(src0 + row*128 + kq));
    }
    asm volatile("cp.async.commit_group;" ::: "memory");
}

// gather S rows [rfirst, rfirst+nrows) for tile t into stage buffer (warp-wide, lane=feature chunk)
__device__ __forceinline__ void gather_s(float* __restrict__ sA_st,
                                         const float* __restrict__ X,
                                         int t, int rfirst, int nrows, int lane) {
    int b = t / TPB;
    int vbase = (t - b*TPB) * 32;
    const float* Xb = X + (size_t)b * Vn * 128 + lane*4;

    for (int rr = 0; rr < nrows; rr += 4) {
        int p[4], e[4];
        float4 aA[4], aB[4];
        #pragma unroll
        for (int q = 0; q < 4; q++) {
            int v = vbase + rfirst + rr + q;
            p[q] = g_rowptr[v];
            e[q] = g_rowptr[v+1];
            aA[q] = make_float4(0,0,0,0);
            aB[q] = make_float4(0,0,0,0);
        }
        bool more = true;
        while (more) {
            more = false;
            #pragma unroll
            for (int q = 0; q < 4; q++) {
                if (p[q] < e[q]) {
                    int j0 = __ldg(&g_col[p[q]]);
                    float4 f = *(const float4*)(Xb + (size_t)j0*128);
                    aA[q].x += f.x; aA[q].y += f.y; aA[q].z += f.z; aA[q].w += f.w;
                    p[q]++;
                    if (p[q] < e[q]) {
                        int j1 = __ldg(&g_col[p[q]]);
                        float4 g4 = *(const float4*)(Xb + (size_t)j1*128);
                        aB[q].x += g4.x; aB[q].y += g4.y; aB[q].z += g4.z; aB[q].w += g4.w;
                        p[q]++;
                    }
                    if (p[q] < e[q]) more = true;
                }
            }
        }
        #pragma unroll
        for (int q = 0; q < 4; q++) {
            int r = rfirst + rr + q;
            float4 s;
            s.x = rnd_tf32(aA[q].x + aB[q].x);
            s.y = rnd_tf32(aA[q].y + aB[q].y);
            s.z = rnd_tf32(aA[q].z + aB[q].z);
            s.w = rnd_tf32(aA[q].w + aB[q].w);
            *(float4*)(sA_st + r*256 + ((128 + lane*4) ^ ((r & 7) << 2))) = s;
        }
    }
}

__global__ void __launch_bounds__(256, 1)
gconv_fused(const float* __restrict__ X,
            const float* __restrict__ Bt0, const float* __restrict__ Bt1,
            const float* __restrict__ bias,
            const float* __restrict__ Dadd,
            float* __restrict__ Y,
            int do_round) {
    extern __shared__ float smf[];
    float* sB    = smf + SB_OFF;
    float* sA    = smf + SA_OFF;
    float* sRed  = smf + SRED_OFF;
    float* sbias = smf + SBIAS_OFF;

    int tid = threadIdx.x;
    int wid = tid >> 5, lane = tid & 31;
    int gidx = lane >> 2, tig = lane & 3;
    int kh = wid >> 2;          // k-half: 0 -> k[0,128), 1 -> k[128,256)
    int ng = wid & 3;           // col group: 32 cols each

    // load weights: sB[n][k], k<128 = W0, k>=128 = W1 (both [n][k] in gmem)
    for (int i4 = tid; i4 < 8192; i4 += 256) {
        int n  = i4 >> 6;                 // 64 float4 per n-row
        int kq = (i4 & 63) << 2;
        float4 v = (kq < 128) ? *(const float4*)(Bt0 + n*128 + kq)
                              : *(const float4*)(Bt1 + n*128 + (kq - 128));
        *(float4*)(sB + n*256 + (kq ^ ((n & 7) << 2))) = v;
    }
    if (tid < 128) sbias[tid] = bias[tid];

    uint32_t sA_u = smem_u32(sA);
    const int grid = gridDim.x;

    // prologue: fill stage 0 for first tile
    int t0 = blockIdx.x;
    if (t0 < NTILES) {
        issue_x(X, t0, 0, tid, sA_u);
        gather_s(sA, X, t0, wid*4, 4, lane);
    }

    int it = 0;
    for (int t = t0; t < NTILES; t += grid, it++) {
        asm volatile("cp.async.wait_group 0;" ::: "memory");
        __syncthreads();   // stage cur (X + S) visible; prev iter fully done

        const float* sAc = sA + (it & 1) * 8192;

        float c[2][4][4];
        #pragma unroll
        for (int mt = 0; mt < 2; mt++)
            #pragma unroll
            for (int nt = 0; nt < 4; nt++)
                #pragma unroll
                for (int q = 0; q < 4; q++) c[mt][nt][q] = 0.0f;

        const int kb0 = kh * 128;
        #pragma unroll 4
        for (int ks = 0; ks < 16; ks++) {
            int kb = kb0 + ks*8;
            uint32_t a[2][4];
            #pragma unroll
            for (int mt = 0; mt < 2; mt++) {
                int r0 = mt*16 + gidx;
                int sw = (r0 & 7) << 2;               // (r0+8)&7 == r0&7
                a[mt][0] = __float_as_uint(sAc[r0*256     + ((kb+tig)   ^ sw)]);
                a[mt][1] = __float_as_uint(sAc[(r0+8)*256 + ((kb+tig)   ^ sw)]);
                a[mt][2] = __float_as_uint(sAc[r0*256     + ((kb+4+tig) ^ sw)]);
                a[mt][3] = __float_as_uint(sAc[(r0+8)*256 + ((kb+4+tig) ^ sw)]);
            }
            uint32_t b[4][2];
            #pragma unroll
            for (int nt = 0; nt < 4; nt++) {
                int n = ng*32 + nt*8 + gidx;
                int sn = (n & 7) << 2;
                b[nt][0] = __float_as_uint(sB[n*256 + ((kb+tig)   ^ sn)]);
                b[nt][1] = __float_as_uint(sB[n*256 + ((kb+4+tig) ^ sn)]);
            }
            #pragma unroll
            for (int mt = 0; mt < 2; mt++)
                #pragma unroll
                for (int nt = 0; nt < 4; nt++)
                    mma_tf32(c[mt][nt], a[mt], b[nt]);
        }

        // k-half 1 writes partials to sRed
        if (kh == 1) {
            float* red = sRed + ng * 1280;   // 32 rows x stride 40
            #pragma unroll
            for (int mt = 0; mt < 2; mt++)
                #pragma unroll
                for (int nt = 0; nt < 4; nt++) {
                    int cl = nt*8 + 2*tig;
                    int r0 = mt*16 + gidx;
                    *(float2*)(red + r0*40 + cl)     = make_float2(c[mt][nt][0], c[mt][nt][1]);
                    *(float2*)(red + (r0+8)*40 + cl) = make_float2(c[mt][nt][2], c[mt][nt][3]);
                }
        }

        // prefetch next tile's X while partials settle
        int tn = t + grid;
        if (tn < NTILES) issue_x(X, tn, (it + 1) & 1, tid, sA_u);

        __syncthreads();   // sRed visible

        if (kh == 0) {
            // reduce + bias (+res) + store
            const float* red = sRed + ng * 1280;
            int tbase = t * 32;
            #pragma unroll
            for (int mt = 0; mt < 2; mt++) {
                #pragma unroll
                for (int i2 = 0; i2 < 2; i2++) {
                    int rl = mt*16 + gidx + i2*8;
                    size_t grow = (size_t)(tbase + rl) * 128;
                    #pragma unroll
                    for (int nt = 0; nt < 4; nt++) {
                        int cl = nt*8 + 2*tig;
                        int cg = ng*32 + cl;
                        float2 pr = *(const float2*)(red + rl*40 + cl);
                        float2 bv = *(const float2*)(sbias + cg);
                        float vx = c[mt][nt][i2*2+0] + pr.x + bv.x;
                        float vy = c[mt][nt][i2*2+1] + pr.y + bv.y;
                        if (Dadd) {
                            float2 dv = *(const float2*)(Dadd + grow + cg);
                            vx += dv.x; vy += dv.y;
                        }
                        if (do_round) { vx = rnd_tf32(vx); vy = rnd_tf32(vy); }
                        *(float2*)(Y + grow + cg) = make_float2(vx, vy);
                    }
                }
            }
        } else {
            // gather next tile's S rows (warps 4-7: 8 rows each)
            if (tn < NTILES)
                gather_s(sA + ((it + 1) & 1) * 8192, X, tn, (wid - 4) * 8, 8, lane);
        }
    }
}

// ---------------- launch ----------------
extern "C" void kernel_launch(void* const* d_in, const int* in_sizes, int n_in,
                              void* d_out, int out_size) {
    const float* img  = (const float*)d_in[0];
    const float* vpos = (const float*)d_in[1];
    const float* vpad = (const float*)d_in[2];
    const int*   edges= (const int*)  d_in[3];
    const float* w0_1 = (const float*)d_in[4];
    const float* b0_1 = (const float*)d_in[5];
    const float* w1_1 = (const float*)d_in[6];
    const float* w0_2 = (const float*)d_in[7];
    const float* b0_2 = (const float*)d_in[8];
    const float* w1_2 = (const float*)d_in[9];
    const float* w0_3 = (const float*)d_in[10];
    const float* b0_3 = (const float*)d_in[11];
    const float* w1_3 = (const float*)d_in[12];
    float* out = (float*)d_out;

    float *pA, *pD, *pBt;
    cudaGetSymbolAddress((void**)&pA,  g_A);
    cudaGetSymbolAddress((void**)&pD,  g_Dk);
    cudaGetSymbolAddress((void**)&pBt, g_Bt);

    const int smem = SMEM_FLOATS * sizeof(float);   // 217600 B
    cudaFuncSetAttribute(gconv_fused, cudaFuncAttributeMaxDynamicSharedMemorySize, smem);

    int nsm = 148;
    cudaDeviceGetAttribute(&nsm, cudaDevAttrMultiProcessorCount, 0);

    // CSR build
    zero_csr<<<(Vn+255)/256, 256>>>();
    count_edges<<<(En+255)/256, 256>>>(edges);
    scan_kernel<<<1, 1024>>>();
    fill_edges<<<(En+255)/256, 256>>>(edges);

    // weights: transpose + round to tf32
    prep_weights<<<64, 256>>>(w0_1, pBt + 0*16384);
    prep_weights<<<64, 256>>>(w1_1, pBt + 1*16384);
    prep_weights<<<64, 256>>>(w0_2, pBt + 2*16384);
    prep_weights<<<64, 256>>>(w1_2, pBt + 3*16384);
    prep_weights<<<64, 256>>>(w0_3, pBt + 4*16384);
    prep_weights<<<64, 256>>>(w1_3, pBt + 5*16384);

    // vert_align (output tf32-rounded)
    transpose_img<<<dim3((HWn+31)/32, Cn/32, Bn), dim3(32,32)>>>(img);
    vert_align_kernel<<<Mn/8, 256>>>(vpos, vpad);   // g_A = round(G)

    // conv1: D = [G|AG] @ [W0;W1] + b0      (rounded)
    gconv_fused<<<nsm, 256, smem>>>(pA, pBt + 0*16384, pBt + 1*16384, b0_1, nullptr, pD, 1);
    // conv2: U = [D|AD] @ [W0;W1] + b0      (rounded; overwrites g_A)
    gconv_fused<<<nsm, 256, smem>>>(pD, pBt + 2*16384, pBt + 3*16384, b0_2, nullptr, pA, 1);
    // conv3 + residual: out = D + [U|AU] @ [W0;W1] + b0
    gconv_fused<<<nsm, 256, smem>>>(pA, pBt + 4*16384, pBt + 5*16384, b0_3, pD, out, 0);
}

// round 5
// speedup vs baseline: 3.0941x; 3.0941x over previous
#include <cuda_runtime.h>
#include <cstdint>

#define Bn 16
#define Vn 40000
#define Cn 128
#define Hn 56
#define Wn 56
#define En 120000
#define Mn (Bn*Vn)          // 640000
#define HWn (Hn*Wn)         // 3136
#define NTILES (Mn/32)      // 20000

// ---------------- device scratch ----------------
__device__ float g_imgT[(size_t)Bn*HWn*Cn];     // [B,H,W,C]
__device__ float g_A [81920000];                // G, later U (tf32-rounded)
__device__ float g_Dk[81920000];                // D (tf32-rounded; residual)
__device__ float g_S [81920000];                // S = A*X (tf32-rounded)
__device__ float g_Bt[6*128*128];               // transposed tf32 weights [n][k]

__device__ int g_deg[Vn];
__device__ int g_cursor[Vn];
__device__ int g_rowptr[Vn+1];
__device__ int g_col[2*En];

// ---------------- helpers ----------------
__device__ __forceinline__ float rnd_tf32(float x) {
    float r;
    asm("cvt.rna.tf32.f32 %0, %1;" : "=f"(r) : "f"(x));
    return r;
}

__device__ __forceinline__ uint32_t smem_u32(const void* p) {
    uint32_t a;
    asm("{ .reg .u64 t; cvta.to.shared.u64 t, %1; cvt.u32.u64 %0, t; }" : "=r"(a) : "l"(p));
    return a;
}

__device__ __forceinline__ void mma_tf32(float* c, const uint32_t* a, const uint32_t* b) {
    asm volatile(
        "mma.sync.aligned.m16n8k8.row.col.f32.tf32.tf32.f32 "
        "{%0,%1,%2,%3}, {%4,%5,%6,%7}, {%8,%9}, {%0,%1,%2,%3};"
        : "+f"(c[0]), "+f"(c[1]), "+f"(c[2]), "+f"(c[3])
        : "r"(a[0]), "r"(a[1]), "r"(a[2]), "r"(a[3]), "r"(b[0]), "r"(b[1]));
}

// ---------------- CSR build ----------------
__global__ void zero_csr() {
    int i = blockIdx.x*blockDim.x + threadIdx.x;
    if (i < Vn) { g_deg[i] = 0; g_cursor[i] = 0; }
}

__global__ void count_edges(const int* __restrict__ edges) {
    int e = blockIdx.x*blockDim.x + threadIdx.x;
    if (e < En) {
        atomicAdd(&g_deg[edges[2*e+0]], 1);
        atomicAdd(&g_deg[edges[2*e+1]], 1);
    }
}

__global__ void scan_kernel() {
    __shared__ int partial[1024];
    int t = threadIdx.x;
    const int CH = (Vn + 1023) / 1024;
    int base = t * CH;
    int s = 0;
    for (int i = 0; i < CH; i++) {
        int idx = base + i;
        if (idx < Vn) s += g_deg[idx];
    }
    partial[t] = s;
    __syncthreads();
    for (int off = 1; off < 1024; off <<= 1) {
        int v = 0;
        if (t >= off) v = partial[t - off];
        __syncthreads();
        partial[t] += v;
        __syncthreads();
    }
    int run = (t == 0) ? 0 : partial[t-1];
    for (int i = 0; i < CH; i++) {
        int idx = base + i;
        if (idx < Vn) { g_rowptr[idx] = run; run += g_deg[idx]; }
    }
    if (t == 1023) g_rowptr[Vn] = run;
}

__global__ void fill_edges(const int* __restrict__ edges) {
    int e = blockIdx.x*blockDim.x + threadIdx.x;
    if (e < En) {
        int i = edges[2*e+0], j = edges[2*e+1];
        int p = atomicAdd(&g_cursor[i], 1);
        g_col[g_rowptr[i] + p] = j;
        int q = atomicAdd(&g_cursor[j], 1);
        g_col[g_rowptr[j] + q] = i;
    }
}

// ---------------- weight prep: Bt[n*128+k] = round_tf32(W[k*128+n]) ----------------
__global__ void prep_weights(const float* __restrict__ W, float* __restrict__ Bt) {
    int i = blockIdx.x*blockDim.x + threadIdx.x;   // 16384
    int n = i >> 7, k = i & 127;
    Bt[i] = rnd_tf32(W[k*128 + n]);
}

// ---------------- image transpose [B,C,H,W] -> [B,H,W,C] ----------------
__global__ void transpose_img(const float* __restrict__ img) {
    __shared__ float tile[32][33];
    int b   = blockIdx.z;
    int hw0 = blockIdx.x * 32;
    int c0  = blockIdx.y * 32;
    int tx = threadIdx.x, ty = threadIdx.y;
    int hw = hw0 + tx, c = c0 + ty;
    if (hw < HWn)
        tile[ty][tx] = img[((size_t)(b*Cn + c))*HWn + hw];
    __syncthreads();
    int hw2 = hw0 + ty, c2 = c0 + tx;
    if (hw2 < HWn)
        g_imgT[((size_t)(b*HWn + hw2))*Cn + c2] = tile[tx][ty];
}

// ---------------- vert_align + add padded -> g_A (tf32-rounded) ----------------
__global__ void vert_align_kernel(const float* __restrict__ vpos,
                                  const float* __restrict__ vpad) {
    int gw   = (blockIdx.x*blockDim.x + threadIdx.x) >> 5;
    int lane = threadIdx.x & 31;
    if (gw >= Mn) return;
    int b = gw / Vn;

    float px = vpos[(size_t)gw*3 + 0];
    float py = vpos[(size_t)gw*3 + 1];
    float x = (px + 1.0f) * 0.5f * (float)(Wn - 1);
    float y = (py + 1.0f) * 0.5f * (float)(Hn - 1);
    float x0f = floorf(x), y0f = floorf(y);
    float wx1 = x - x0f, wx0 = 1.0f - wx1;
    float wy1 = y - y0f, wy0 = 1.0f - wy1;
    int x0 = (int)x0f, y0 = (int)y0f;

    float4 acc = ((const float4*)(vpad + (size_t)gw*Cn))[lane];

    int   xs_[4] = { x0, x0+1, x0,   x0+1 };
    int   ys_[4] = { y0, y0,   y0+1, y0+1 };
    float ws_[4] = { wx0*wy0, wx1*wy0, wx0*wy1, wx1*wy1 };

    #pragma unroll
    for (int t = 0; t < 4; t++) {
        int xi = xs_[t], yi = ys_[t];
        bool inb = (xi >= 0) && (xi < Wn) && (yi >= 0) && (yi < Hn);
        float wgt = inb ? ws_[t] : 0.0f;
        if (wgt != 0.0f) {
            float4 f = ((const float4*)(g_imgT + ((size_t)((b*Hn + yi)*Wn + xi))*Cn))[lane];
            acc.x += wgt*f.x; acc.y += wgt*f.y; acc.z += wgt*f.z; acc.w += wgt*f.w;
        }
    }
    acc.x = rnd_tf32(acc.x); acc.y = rnd_tf32(acc.y);
    acc.z = rnd_tf32(acc.z); acc.w = rnd_tf32(acc.w);
    ((float4*)(g_A + (size_t)gw*Cn))[lane] = acc;
}

// ---------------- agg: S[b,v] = rnd( sum_{j in N(v)} X[b,j] ) ----------------
__global__ void agg_kernel(const float* __restrict__ X, float* __restrict__ S) {
    int gw   = (blockIdx.x*blockDim.x + threadIdx.x) >> 5;
    int lane = threadIdx.x & 31;
    if (gw >= Mn) return;
    int b = gw / Vn;
    int v = gw - b*Vn;

    const float* Xb = X + (size_t)b*Vn*Cn + lane*4;
    float4 acc = make_float4(0,0,0,0);
    int s = g_rowptr[v];
    int e = g_rowptr[v+1];
    for (int p = s; p < e; p++) {
        int j = __ldg(&g_col[p]);
        float4 t = *(const float4*)(Xb + (size_t)j*Cn);
        acc.x += t.x; acc.y += t.y; acc.z += t.z; acc.w += t.w;
    }
    acc.x = rnd_tf32(acc.x); acc.y = rnd_tf32(acc.y);
    acc.z = rnd_tf32(acc.z); acc.w = rnd_tf32(acc.w);
    *(float4*)(S + (size_t)gw*Cn + lane*4) = acc;
}

// ---------------- fused conv GEMM: Y = [X|S](32x256) @ Wcat^T(256x128) + b0 (+Dadd) ----------------
// SMEM floats: sB[128n x 256k] swz | sA[2][32 x 256] swz | sRed[4][32][34] | sbias[128]
#define SB_OFF    0
#define SA_OFF    32768
#define SRED_OFF  49152
#define SBIAS_OFF 53504
#define SMEM_FLOATS 53632      // 214528 B

__device__ __forceinline__ void issue_xs(const float* __restrict__ X,
                                         const float* __restrict__ S,
                                         int t, int buf, int tid, uint32_t sA_u) {
    size_t rb = (size_t)t * 32;
    uint32_t dbase = sA_u + (uint32_t)buf * 32768u;   // bytes (8192 floats per stage)
    #pragma unroll
    for (int j = 0; j < 4; j++) {
        int i4 = tid + j*256;                // 0..1023
        int row = i4 >> 5;                   // 0..31
        int kq  = (i4 & 31) << 2;            // 0..124
        uint32_t off = (uint32_t)((row << 8) + (kq ^ ((row & 7) << 2))) * 4u;
        asm volatile("cp.async.cg.shared.global [%0], [%1], 16;"
            :: "r"(dbase + off), "l"(X + (rb + row)*128 + kq));
    }
    #pragma unroll
    for (int j = 0; j < 4; j++) {
        int i4 = tid + j*256;
        int row = i4 >> 5;
        int kq  = (i4 & 31) << 2;
        uint32_t off = (uint32_t)((row << 8) + ((128 + kq) ^ ((row & 7) << 2))) * 4u;
        asm volatile("cp.async.cg.shared.global [%0], [%1], 16;"
            :: "r"(dbase + off), "l"(S + (rb + row)*128 + kq));
    }
    asm volatile("cp.async.commit_group;" ::: "memory");
}

__global__ void __launch_bounds__(256, 1)
gconv_gemm(const float* __restrict__ X, const float* __restrict__ S,
           const float* __restrict__ Bt0, const float* __restrict__ Bt1,
           const float* __restrict__ bias,
           const float* __restrict__ Dadd,
           float* __restrict__ Y,
           int do_round) {
    extern __shared__ float smf[];
    float* sB    = smf + SB_OFF;
    float* sA    = smf + SA_OFF;
    float* sRed  = smf + SRED_OFF;
    float* sbias = smf + SBIAS_OFF;

    int tid = threadIdx.x;
    int wid = tid >> 5, lane = tid & 31;
    int gidx = lane >> 2, tig = lane & 3;
    int kh = wid >> 2;          // k-half: 0 -> k[0,128)=W0 path, 1 -> k[128,256)=W1 path
    int ng = wid & 3;           // col group: 32 cols each

    // weights: sB[n][k]: k<128 = W0t, k>=128 = W1t
    for (int i4 = tid; i4 < 8192; i4 += 256) {
        int n  = i4 >> 6;
        int kq = (i4 & 63) << 2;
        float4 v = (kq < 128) ? *(const float4*)(Bt0 + n*128 + kq)
                              : *(const float4*)(Bt1 + n*128 + (kq - 128));
        *(float4*)(sB + n*256 + (kq ^ ((n & 7) << 2))) = v;
    }
    if (tid < 128) sbias[tid] = bias[tid];

    uint32_t sA_u = smem_u32(sA);
    const int grid = gridDim.x;

    int t0 = blockIdx.x;
    if (t0 < NTILES) issue_xs(X, S, t0, 0, tid, sA_u);

    int it = 0;
    for (int t = t0; t < NTILES; t += grid, it++) {
        int tn = t + grid;
        if (tn < NTILES) {
            issue_xs(X, S, tn, (it + 1) & 1, tid, sA_u);
            asm volatile("cp.async.wait_group 1;" ::: "memory");
        } else {
            asm volatile("cp.async.wait_group 0;" ::: "memory");
        }
        __syncthreads();   // cur stage visible; prev iter epilogue done (sRed free)

        const float* sAc = sA + (it & 1) * 8192;

        float c[2][4][4];
        #pragma unroll
        for (int mt = 0; mt < 2; mt++)
            #pragma unroll
            for (int nt = 0; nt < 4; nt++)
                #pragma unroll
                for (int q = 0; q < 4; q++) c[mt][nt][q] = 0.0f;

        const int kb0 = kh * 128;
        #pragma unroll 4
        for (int ks = 0; ks < 16; ks++) {
            int kb = kb0 + ks*8;
            uint32_t a[2][4];
            #pragma unroll
            for (int mt = 0; mt < 2; mt++) {
                int r0 = mt*16 + gidx;
                int sw = (r0 & 7) << 2;
                a[mt][0] = __float_as_uint(sAc[r0*256     + ((kb+tig)   ^ sw)]);
                a[mt][1] = __float_as_uint(sAc[(r0+8)*256 + ((kb+tig)   ^ sw)]);
                a[mt][2] = __float_as_uint(sAc[r0*256     + ((kb+4+tig) ^ sw)]);
                a[mt][3] = __float_as_uint(sAc[(r0+8)*256 + ((kb+4+tig) ^ sw)]);
            }
            uint32_t b[4][2];
            #pragma unroll
            for (int nt = 0; nt < 4; nt++) {
                int n = ng*32 + nt*8 + gidx;
                int sn = (n & 7) << 2;
                b[nt][0] = __float_as_uint(sB[n*256 + ((kb+tig)   ^ sn)]);
                b[nt][1] = __float_as_uint(sB[n*256 + ((kb+4+tig) ^ sn)]);
            }
            #pragma unroll
            for (int mt = 0; mt < 2; mt++)
                #pragma unroll
                for (int nt = 0; nt < 4; nt++)
                    mma_tf32(c[mt][nt], a[mt], b[nt]);
        }

        // k-half 1 publishes partials
        if (kh == 1) {
            float* red = sRed + ng * 1088;   // 32 rows x stride 34
            #pragma unroll
            for (int mt = 0; mt < 2; mt++)
                #pragma unroll
                for (int nt = 0; nt < 4; nt++) {
                    int cl = nt*8 + 2*tig;
                    int r0 = mt*16 + gidx;
                    *(float2*)(red + r0*34 + cl)     = make_float2(c[mt][nt][0], c[mt][nt][1]);
                    *(float2*)(red + (r0+8)*34 + cl) = make_float2(c[mt][nt][2], c[mt][nt][3]);
                }
        }
        __syncthreads();   // sRed visible

        if (kh == 0) {
            const float* red = sRed + ng * 1088;
            int tbase = t * 32;
            #pragma unroll
            for (int mt = 0; mt < 2; mt++) {
                #pragma unroll
                for (int i2 = 0; i2 < 2; i2++) {
                    int rl = mt*16 + gidx + i2*8;
                    size_t grow = (size_t)(tbase + rl) * 128;
                    #pragma unroll
                    for (int nt = 0; nt < 4; nt++) {
                        int cl = nt*8 + 2*tig;
                        int cg = ng*32 + cl;
                        float2 pr = *(const float2*)(red + rl*34 + cl);
                        float2 bv = *(const float2*)(sbias + cg);
                        float vx = c[mt][nt][i2*2+0] + pr.x + bv.x;
                        float vy = c[mt][nt][i2*2+1] + pr.y + bv.y;
                        if (Dadd) {
                            float2 dv = *(const float2*)(Dadd + grow + cg);
                            vx += dv.x; vy += dv.y;
                        }
                        if (do_round) { vx = rnd_tf32(vx); vy = rnd_tf32(vy); }
                        *(float2*)(Y + grow + cg) = make_float2(vx, vy);
                    }
                }
            }
        }
        // NOTE: next iteration's __syncthreads (after wait_group) orders
        // sRed reuse and sA-stage overwrite against this epilogue.
    }
}

// ---------------- launch ----------------
extern "C" void kernel_launch(void* const* d_in, const int* in_sizes, int n_in,
                              void* d_out, int out_size) {
    const float* img  = (const float*)d_in[0];
    const float* vpos = (const float*)d_in[1];
    const float* vpad = (const float*)d_in[2];
    const int*   edges= (const int*)  d_in[3];
    const float* w0_1 = (const float*)d_in[4];
    const float* b0_1 = (const float*)d_in[5];
    const float* w1_1 = (const float*)d_in[6];
    const float* w0_2 = (const float*)d_in[7];
    const float* b0_2 = (const float*)d_in[8];
    const float* w1_2 = (const float*)d_in[9];
    const float* w0_3 = (const float*)d_in[10];
    const float* b0_3 = (const float*)d_in[11];
    const float* w1_3 = (const float*)d_in[12];
    float* out = (float*)d_out;

    float *pA, *pD, *pS, *pBt;
    cudaGetSymbolAddress((void**)&pA,  g_A);
    cudaGetSymbolAddress((void**)&pD,  g_Dk);
    cudaGetSymbolAddress((void**)&pS,  g_S);
    cudaGetSymbolAddress((void**)&pBt, g_Bt);

    const int smem = SMEM_FLOATS * sizeof(float);   // 214528 B
    cudaFuncSetAttribute(gconv_gemm, cudaFuncAttributeMaxDynamicSharedMemorySize, smem);

    int nsm = 148;
    cudaDeviceGetAttribute(&nsm, cudaDevAttrMultiProcessorCount, 0);

    // CSR build
    zero_csr<<<(Vn+255)/256, 256>>>();
    count_edges<<<(En+255)/256, 256>>>(edges);
    scan_kernel<<<1, 1024>>>();
    fill_edges<<<(En+255)/256, 256>>>(edges);

    // weights: transpose + round to tf32
    prep_weights<<<64, 256>>>(w0_1, pBt + 0*16384);
    prep_weights<<<64, 256>>>(w1_1, pBt + 1*16384);
    prep_weights<<<64, 256>>>(w0_2, pBt + 2*16384);
    prep_weights<<<64, 256>>>(w1_2, pBt + 3*16384);
    prep_weights<<<64, 256>>>(w0_3, pBt + 4*16384);
    prep_weights<<<64, 256>>>(w1_3, pBt + 5*16384);

    // vert_align (output tf32-rounded)
    transpose_img<<<dim3((HWn+31)/32, Cn/32, Bn), dim3(32,32)>>>(img);
    vert_align_kernel<<<Mn/8, 256>>>(vpos, vpad);   // g_A = round(G)

    // conv1: D = [G|A·G] @ [W0;W1] + b0
    agg_kernel<<<Mn/8, 256>>>(pA, pS);
    gconv_gemm<<<nsm, 256, smem>>>(pA, pS, pBt + 0*16384, pBt + 1*16384, b0_1, nullptr, pD, 1);

    // conv2: U = [D|A·D] @ [W0;W1] + b0   (overwrites g_A)
    agg_kernel<<<Mn/8, 256>>>(pD, pS);
    gconv_gemm<<<nsm, 256, smem>>>(pD, pS, pBt + 2*16384, pBt + 3*16384, b0_2, nullptr, pA, 1);

    // conv3 + residual: out = D + [U|A·U] @ [W0;W1] + b0
    agg_kernel<<<Mn/8, 256>>>(pA, pS);
    gconv_gemm<<<nsm, 256, smem>>>(pA, pS, pBt + 4*16384, pBt + 5*16384, b0_3, pD, out, 0);
}